// round 16
// baseline (speedup 1.0000x reference)
#include <cuda_runtime.h>
#include <cuda_fp16.h>
#include <mma.h>
#include <cstdint>

using namespace nvcuda;

// Problem constants (shapes fixed by the reference)
#define NNODES 15360       // 512 graphs * 30 nodes
#define HID 64
#define NPG 30             // nodes per graph
#define NBR 41             // branches per graph
#define NEPG 82            // edges per graph (bidirectional)
#define NLAYERS 5
#define QCOLS 2112         // 32*64 (w-part) + 64 (b2-part)
#define APAD 72            // padded smem stride for A (halfs)
#define BPAD 72            // padded smem stride for B (halfs)
#define OPAD 200           // padded smem stride for output stage (halfs, 400B)
#define FTHREADS 512       // k_fused block size
#define BN_EPS 1e-5f

// k_qwmma smem: union { [As 128x72 | Bs 2x96x72] ; Out 128x200 } halfs
#define QSMEM (128 * OPAD * 2)   // 51200 bytes

// k_fused dynamic smem layout (bytes)
#define F_SH     0                   // float[1920]   h tile
#define F_SH16   7680                // half[32*72]   fp16 h (padded)
#define F_SAGG   12288               // float[1920]   agg
#define F_SZ     19968               // float[96*32]  z
#define F_EA     32256               // half[96*136]  ea
#define F_W1H    58368               // half[128*40]  W1 fp16
#define F_WRH    68608               // half[64*72]   Wr fp16
#define F_RES    77824               // float[32*64]  R = h @ Wr
#define F_SDEG   86016               // float[30]
#define F_SSE    86136               // int[82]
#define F_SDE    86464               // int[82]
#define F_SOUT   86792               // int[30]  out-degree
#define F_SSTART 86912               // int[31]  CSR starts
#define F_SCNT   87040               // int[30]  scatter counters
#define F_EORD   87160               // int[82]  edge ids by src
#define F_TOT    87488

// ---------------- scratch (device globals; no allocation allowed) -----------
__device__ float g_h0[NNODES * HID];
__device__ float g_h1[NNODES * HID];
__device__ __half g_Q[(size_t)NNODES * QCOLS];              // ~65 MB fp16
__device__ __half g_hs[(size_t)NNODES * HID];               // fp16 h
__device__ __half g_Ws[(size_t)NLAYERS * QCOLS * HID];      // B  [l][n][64] fp16

// ---------------- prep kernels ----------------------------------------------
// Ws[l][n][k] = fp16(W2p[k][n]); cols 0..2047 from W2, 2048..2111 from b2
__global__ void k_wsplit(const float* __restrict__ W2, const float* __restrict__ b2,
                         __half* __restrict__ Ws, int lo0, int hi0) {
    int idx = lo0 + blockIdx.x * blockDim.x + threadIdx.x;
    if (idx >= hi0) return;
    int k = idx & 63;
    int n = (idx >> 6) % QCOLS;
    int l = idx / (QCOLS * HID);
    float v;
    if (n < 2048) {
        int j = n >> 6, o = n & 63;
        v = W2[(size_t)(l * 32 + j) * 4096 + k * 64 + o];
    } else {
        v = b2[(size_t)l * 4096 + k * 64 + (n - 2048)];
    }
    Ws[idx] = __float2half_rn(v);
}

// h0 = x @ Wp + bp  (+ fp16 copy of h0)
__global__ void k_proj(const float* __restrict__ x, const float* __restrict__ Wp,
                       const float* __restrict__ bp, float* __restrict__ h,
                       __half* __restrict__ hs, int N) {
    int t = blockIdx.x * blockDim.x + threadIdx.x;
    if (t >= N * HID) return;
    int n = t >> 6, c = t & 63;
    const float* xr = x + n * 8;
    float acc = bp[c];
#pragma unroll
    for (int k = 0; k < 8; k++) acc += xr[k] * Wp[k * 64 + c];
    h[t] = acc;
    hs[t] = __float2half_rn(acc);
}

// ---------------- WMMA fp16 GEMM: Q = h(15360x64) @ W^T(64x2112) -------------
// block: 128 M x (2 x 96) N subtiles; fp16 accum; smem-staged coalesced store.
__global__ __launch_bounds__(256, 4) void k_qwmma(const __half* __restrict__ A,
                                                  const __half* __restrict__ B,
                                                  __half* __restrict__ Q) {
    extern __shared__ __half sm[];
    __half* As  = sm;                          // 128 x APAD
    __half* Bs  = sm + 128 * APAD;             // 2 x (96 x BPAD)
    __half* Os  = sm;                          // aliased output stage 128 x OPAD
    const int m0 = blockIdx.y * 128;
    const int n0 = blockIdx.x * 192;
    const int t = threadIdx.x;

    for (int i = t; i < 128 * 8; i += 256) {
        int r = i >> 3, c = (i & 7) * 8;
        *(uint4*)(As + r * APAD + c) = *(const uint4*)(A + (size_t)(m0 + r) * HID + c);
    }
    for (int i = t; i < 2 * 96 * 8; i += 256) {
        int s = i / 768;
        int r = (i % 768) >> 3, c = (i & 7) * 8;
        *(uint4*)(Bs + s * 96 * BPAD + r * BPAD + c) =
            *(const uint4*)(B + (size_t)(n0 + s * 96 + r) * HID + c);
    }
    __syncthreads();

    const int w = t >> 5;
    const int mw = (w & 3) * 32;
    const int nw = (w >> 2) * 48;

    wmma::fragment<wmma::accumulator, 16, 16, 16, __half> acc[2][2][3];
#pragma unroll
    for (int s = 0; s < 2; s++) {
        const __half* Bsub = Bs + s * 96 * BPAD;
#pragma unroll
        for (int i = 0; i < 2; i++)
#pragma unroll
            for (int j = 0; j < 3; j++)
                wmma::fill_fragment(acc[s][i][j], __float2half(0.f));
#pragma unroll
        for (int kk = 0; kk < 4; kk++) {
            wmma::fragment<wmma::matrix_b, 16, 16, 16, __half, wmma::col_major> bf[3];
#pragma unroll
            for (int j = 0; j < 3; j++)
                wmma::load_matrix_sync(bf[j], Bsub + (nw + j * 16) * BPAD + kk * 16, BPAD);
            wmma::fragment<wmma::matrix_a, 16, 16, 16, __half, wmma::row_major> af[2];
#pragma unroll
            for (int i = 0; i < 2; i++)
                wmma::load_matrix_sync(af[i], As + (mw + i * 16) * APAD + kk * 16, APAD);
#pragma unroll
            for (int i = 0; i < 2; i++)
#pragma unroll
                for (int j = 0; j < 3; j++)
                    wmma::mma_sync(acc[s][i][j], af[i], bf[j], acc[s][i][j]);
        }
    }
    __syncthreads();  // operands dead; Os may overwrite As/Bs

#pragma unroll
    for (int s = 0; s < 2; s++)
#pragma unroll
        for (int i = 0; i < 2; i++)
#pragma unroll
            for (int j = 0; j < 3; j++)
                wmma::store_matrix_sync(
                    Os + (mw + i * 16) * OPAD + s * 96 + nw + j * 16,
                    acc[s][i][j], OPAD, wmma::mem_row_major);
    __syncthreads();

    for (int i = t; i < 128 * 24; i += 256) {
        int r = i / 24, c = (i % 24) * 8;
        *(uint4*)(Q + (size_t)(m0 + r) * QCOLS + n0 + c) = *(const uint4*)(Os + r * OPAD + c);
    }
}

// ---------------- fused per-graph layer kernel --------------------------------
// z + R via WMMA, CSR by src, warp-per-src-node msg gather, node update
__global__ __launch_bounds__(FTHREADS, 2) void k_fused(
    const float* __restrict__ h, const int* __restrict__ src, const int* __restrict__ dst,
    const __half* __restrict__ Qh, const float* __restrict__ W1l, const float* __restrict__ b1l,
    const float* __restrict__ Wr, const float* __restrict__ br,
    const float* __restrict__ gamma, const float* __restrict__ beta,
    const float* __restrict__ rmean, const float* __restrict__ rvar,
    float* __restrict__ hout, __half* __restrict__ hs, int E2) {
    extern __shared__ char smraw[];
    float* sh     = (float*)(smraw + F_SH);
    __half* sh16  = (__half*)(smraw + F_SH16);
    float* sagg   = (float*)(smraw + F_SAGG);
    float* sz     = (float*)(smraw + F_SZ);
    __half* ea    = (__half*)(smraw + F_EA);
    __half* w1h   = (__half*)(smraw + F_W1H);
    __half* wrh   = (__half*)(smraw + F_WRH);
    float* Rbuf   = (float*)(smraw + F_RES);
    float* sdeg   = (float*)(smraw + F_SDEG);
    int* sse      = (int*)(smraw + F_SSE);
    int* sde      = (int*)(smraw + F_SDE);
    int* souts    = (int*)(smraw + F_SOUT);
    int* sstart   = (int*)(smraw + F_SSTART);
    int* scnt     = (int*)(smraw + F_SCNT);
    int* eord     = (int*)(smraw + F_EORD);

    const int g = blockIdx.x;
    const int tid = threadIdx.x;
    const int w = tid >> 5;
    const int lane = tid & 31;
    const int nbase = g * NPG;

    // phase A: stage h (fp32 + fp16), weights, zero agg/deg/counters, edges
    for (int i = tid; i < NPG * HID; i += FTHREADS) {
        float v = h[nbase * HID + i];
        sh[i] = v;
        sagg[i] = 0.f;
    }
    for (int i = tid; i < 32 * 72; i += FTHREADS) {
        int r = i / 72, c = i - r * 72;
        __half v = __float2half_rn(0.f);
        if (r < NPG && c < 64) v = __float2half_rn(h[nbase * HID + r * 64 + c]);
        sh16[i] = v;
    }
    for (int i = tid; i < 128 * 32; i += FTHREADS)
        w1h[(i >> 5) * 40 + (i & 31)] = __float2half_rn(W1l[i]);
    for (int i = tid; i < 64 * 64; i += FTHREADS)
        wrh[(i >> 6) * 72 + (i & 63)] = __float2half_rn(Wr[i]);
    if (tid < NPG) { sdeg[tid] = 0.f; souts[tid] = 0; scnt[tid] = 0; }
    if (tid >= 128 && tid < 128 + NEPG) {
        int k = tid - 128;
        int ei = (k < NBR) ? g * NBR + k : E2 + g * NBR + (k - NBR);
        sse[k] = src[ei] - nbase;
        sde[k] = dst[ei] - nbase;
    }
    __syncthreads();

    // phase B: degree + out-degree atomics, build ea[96][136]
    if (tid < NEPG) {
        atomicAdd(&sdeg[sde[tid]], 1.0f);
        atomicAdd(&souts[sse[tid]], 1);
    }
    for (int i = tid; i < 96 * 128; i += FTHREADS) {
        int k = i >> 7, c = i & 127;
        float v = 0.f;
        if (k < NEPG) {
            int node = (c < 64) ? sse[k] : sde[k];
            v = sh[node * 64 + (c & 63)];
        }
        ea[k * 136 + c] = __float2half_rn(v);
    }
    __syncthreads();

    // phase B2: warp 0 inclusive-scan of out-degrees -> sstart[0..30]
    if (w == 0) {
        int val = (lane < NPG) ? souts[lane] : 0;
#pragma unroll
        for (int off = 1; off < 32; off <<= 1) {
            int y = __shfl_up_sync(0xffffffffu, val, off);
            if (lane >= off) val += y;
        }
        if (lane < NPG) sstart[lane + 1] = val;
        if (lane == 0) sstart[0] = 0;
    }
    __syncthreads();

    // phase D: warps 0-11: z = ea @ W1; warps 12-15: R = h @ Wr; + CSR scatter
    if (tid < NEPG) {
        int s = sse[tid];
        int pos = atomicAdd(&scnt[s], 1);
        eord[sstart[s] + pos] = tid;
    }
    if (w < 12) {
        int mt = w >> 1, nt = w & 1;
        wmma::fragment<wmma::accumulator, 16, 16, 16, float> acc;
        wmma::fill_fragment(acc, 0.f);
#pragma unroll
        for (int kk = 0; kk < 8; kk++) {
            wmma::fragment<wmma::matrix_a, 16, 16, 16, __half, wmma::row_major> af;
            wmma::fragment<wmma::matrix_b, 16, 16, 16, __half, wmma::row_major> bf;
            wmma::load_matrix_sync(af, ea + (mt * 16) * 136 + kk * 16, 136);
            wmma::load_matrix_sync(bf, w1h + (kk * 16) * 40 + nt * 16, 40);
            wmma::mma_sync(acc, af, bf, acc);
        }
        wmma::store_matrix_sync(sz + mt * 16 * 32 + nt * 16, acc, 32, wmma::mem_row_major);
    } else {
#pragma unroll
        for (int rep = 0; rep < 2; rep++) {
            int T = (w - 12) + rep * 4;      // 0..7
            int mt = T >> 2, nt = T & 3;
            wmma::fragment<wmma::accumulator, 16, 16, 16, float> acc;
            wmma::fill_fragment(acc, 0.f);
#pragma unroll
            for (int kk = 0; kk < 4; kk++) {
                wmma::fragment<wmma::matrix_a, 16, 16, 16, __half, wmma::row_major> af;
                wmma::fragment<wmma::matrix_b, 16, 16, 16, __half, wmma::row_major> bf;
                wmma::load_matrix_sync(af, sh16 + (mt * 16) * 72 + kk * 16, 72);
                wmma::load_matrix_sync(bf, wrh + (kk * 16) * 72 + nt * 16, 72);
                wmma::mma_sync(acc, af, bf, acc);
            }
            wmma::store_matrix_sync(Rbuf + mt * 16 * 64 + nt * 16, acc, 64,
                                    wmma::mem_row_major);
        }
    }
    __syncthreads();

    // phase F: warp per src node; Q row cached in registers across its edges
    const int c = lane & 7;    // o-chunk: outputs c*8 .. c*8+7
    const int jo = lane >> 3;  // j offset within group of 4
    const int o = c * 8 + jo * 2;
    const float b1v = b1l[lane];
    for (int n = w; n < NPG; n += FTHREADS / 32) {
        int e0 = sstart[n], e1 = sstart[n + 1];
        if (e0 == e1) continue;
        const __half* Qs = Qh + (size_t)(nbase + n) * QCOLS;
        uint4 qreg[8];
#pragma unroll
        for (int j0 = 0; j0 < 8; j0++)
            qreg[j0] = *(const uint4*)(Qs + (j0 * 4 + jo) * 64 + c * 8);
        float2 bias = __half22float2(*(const half2*)(Qs + 2048 + o));
        for (int ee = e0; ee < e1; ee++) {
            int e = eord[ee];
            int d = sde[e];
            float zval = fmaxf(sz[e * 32 + lane] + b1v, 0.f);
            float acc[8];
#pragma unroll
            for (int i = 0; i < 8; i++) acc[i] = 0.f;
#pragma unroll
            for (int j0 = 0; j0 < 8; j0++) {
                float zz = __shfl_sync(0xffffffffu, zval, j0 * 4 + jo);
                const half2* qh = (const half2*)&qreg[j0];
#pragma unroll
                for (int i = 0; i < 4; i++) {
                    float2 f = __half22float2(qh[i]);
                    acc[2 * i] += zz * f.x;
                    acc[2 * i + 1] += zz * f.y;
                }
            }
#pragma unroll
            for (int i = 0; i < 8; i++) {
                acc[i] += __shfl_xor_sync(0xffffffffu, acc[i], 8);
                acc[i] += __shfl_xor_sync(0xffffffffu, acc[i], 16);
            }
            atomicAdd(&sagg[d * 64 + o], acc[jo * 2] + bias.x);
            atomicAdd(&sagg[d * 64 + o + 1], acc[jo * 2 + 1] + bias.y);
        }
    }
    __syncthreads();

    // phase H: elementwise node update (root GEMM already in Rbuf)
    for (int i = tid; i < NPG * HID; i += FTHREADS) {
        int n = i >> 6, cc = i & 63;
        float h2 = sagg[i] / fmaxf(sdeg[n], 1.0f) + Rbuf[n * 64 + cc] + br[cc];
        float scale = gamma[cc] * rsqrtf(rvar[cc] + BN_EPS);
        h2 = (h2 - rmean[cc]) * scale + beta[cc];
        float r = fmaxf(h2, 0.f) + sh[i];
        hout[nbase * HID + i] = r;
        hs[nbase * HID + i] = __float2half_rn(r);
    }
}

// out[i] = relu([h[u]|h[v]] @ Wm1 + bm1) @ Wm2 + bm2 ; one warp per output row
__global__ void k_final(const float* __restrict__ h, const int* __restrict__ bu,
                        const int* __restrict__ bv, const float* __restrict__ Wm1,
                        const float* __restrict__ bm1, const float* __restrict__ Wm2,
                        const float* __restrict__ bm2, float* __restrict__ out,
                        int nout, int B, int npg) {
    int i = (blockIdx.x * blockDim.x + threadIdx.x) >> 5;
    int lane = threadIdx.x & 31;
    if (i >= nout) return;
    int g = i / B, b = i - g * B;
    int u = bu[b] + g * npg;
    int v = bv[b] + g * npg;
    const float* hu = h + (size_t)u * 64;
    const float* hv = h + (size_t)v * 64;
    float a0 = bm1[lane], a1 = bm1[lane + 32];
#pragma unroll
    for (int k = 0; k < 64; k++) {
        float x0 = hu[k];
        a0 += x0 * Wm1[k * 64 + lane];
        a1 += x0 * Wm1[k * 64 + lane + 32];
    }
#pragma unroll
    for (int k = 0; k < 64; k++) {
        float x1 = hv[k];
        a0 += x1 * Wm1[(64 + k) * 64 + lane];
        a1 += x1 * Wm1[(64 + k) * 64 + lane + 32];
    }
    float r = fmaxf(a0, 0.f) * Wm2[lane] + fmaxf(a1, 0.f) * Wm2[lane + 32];
#pragma unroll
    for (int off = 16; off; off >>= 1) r += __shfl_down_sync(0xffffffffu, r, off);
    if (lane == 0) out[i] = r + bm2[0];
}

extern "C" void kernel_launch(void* const* d_in, const int* in_sizes, int n_in,
                              void* d_out, int out_size) {
    const float* x   = (const float*)d_in[0];
    const int* eidx  = (const int*)d_in[1];
    const int* bu    = (const int*)d_in[2];
    const int* bv    = (const int*)d_in[3];
    int base = (in_sizes[4] == 1) ? 5 : 4;
    const float* Wp    = (const float*)d_in[base + 0];
    const float* bp    = (const float*)d_in[base + 1];
    const float* W1    = (const float*)d_in[base + 2];
    const float* b1    = (const float*)d_in[base + 3];
    const float* W2    = (const float*)d_in[base + 4];
    const float* b2    = (const float*)d_in[base + 5];
    const float* Wr    = (const float*)d_in[base + 6];
    const float* br    = (const float*)d_in[base + 7];
    const float* gamma = (const float*)d_in[base + 8];
    const float* beta  = (const float*)d_in[base + 9];
    const float* rmean = (const float*)d_in[base + 10];
    const float* rvar  = (const float*)d_in[base + 11];
    const float* Wm1   = (const float*)d_in[base + 12];
    const float* bm1   = (const float*)d_in[base + 13];
    const float* Wm2   = (const float*)d_in[base + 14];
    const float* bm2   = (const float*)d_in[base + 15];

    const int Nn = in_sizes[0] / 8;     // 15360
    const int E  = in_sizes[1] / 2;     // 41984
    const int B  = in_sizes[2];         // 41
    const int G  = out_size / B;        // 512
    const int npg = Nn / G;             // 30
    const int* src = eidx;
    const int* dst = eidx + E;
    const int E2 = E / 2;

    static float *p_h0 = nullptr, *p_h1;
    static __half *p_Q, *p_hs, *p_Ws;
    if (!p_h0) {
        cudaGetSymbolAddress((void**)&p_h0, g_h0);
        cudaGetSymbolAddress((void**)&p_h1, g_h1);
        cudaGetSymbolAddress((void**)&p_Q, g_Q);
        cudaGetSymbolAddress((void**)&p_hs, g_hs);
        cudaGetSymbolAddress((void**)&p_Ws, g_Ws);
        cudaFuncSetAttribute(k_qwmma, cudaFuncAttributeMaxDynamicSharedMemorySize, QSMEM);
        cudaFuncSetAttribute(k_fused, cudaFuncAttributeMaxDynamicSharedMemorySize, F_TOT);
    }

    // launches: 0=proj, 1=wsplit, 2=qwmma(l0), 3=fused(l0), 4=qwmma(l1),
    // 5=fused(l1) <- ncu -s 5 profiles the new k_fused
    const int WTOT = NLAYERS * QCOLS * HID;
    k_proj<<<(Nn * HID + 255) / 256, 256>>>(x, Wp, bp, p_h0, p_hs, Nn);
    k_wsplit<<<(WTOT + 255) / 256, 256>>>(W2, b2, p_Ws, 0, WTOT);

    float* cur = p_h0;
    float* nxt = p_h1;
    dim3 gq(QCOLS / 192, Nn / 128);
    for (int l = 0; l < NLAYERS; l++) {
        k_qwmma<<<gq, 256, QSMEM>>>(p_hs, p_Ws + (size_t)l * QCOLS * HID, p_Q);
        k_fused<<<G, FTHREADS, F_TOT>>>(cur, src, dst, p_Q,
                            W1 + (size_t)l * 128 * 32, b1 + (size_t)l * 32,
                            Wr + (size_t)l * 64 * 64, br + (size_t)l * 64,
                            gamma + (size_t)l * 64, beta + (size_t)l * 64,
                            rmean + (size_t)l * 64, rvar + (size_t)l * 64,
                            nxt, p_hs, E2);
        float* tmp = cur; cur = nxt; nxt = tmp;
    }
    k_final<<<(out_size + 7) / 8, 256>>>(cur, bu, bv, Wm1, bm1, Wm2, bm2,
                                         (float*)d_out, out_size, B, npg);
}